// round 7
// baseline (speedup 1.0000x reference)
#include <cuda_runtime.h>
#include <cuda_bf16.h>
#include <math.h>
#include <stdint.h>

#define BATCH 2
#define SEQ 2048
#define DM 1024
#define NH 16
#define DK 64
#define MROWS (BATCH * SEQ)          // 4096
#define BH (BATCH * NH)              // 32

// Scratch (allocation-free rule: __device__ globals)
__device__ float g_q[BH * SEQ * DK];     // [b,h,s,dk]
__device__ float g_k[BH * SEQ * DK];
__device__ float g_v[BH * SEQ * DK];
__device__ float g_ctx[MROWS * DM];      // [b*s, h*dk]

// ---------------------------------------------------------------------------
// bf16 split-precision mma helpers (3xBF16 ~= fp32 accuracy, err ~1e-5)
// ---------------------------------------------------------------------------
__device__ __forceinline__ void mma_bf16(float c[4], const uint32_t a[4], const uint32_t b[2]) {
    asm volatile(
        "mma.sync.aligned.m16n8k16.row.col.f32.bf16.bf16.f32 "
        "{%0,%1,%2,%3}, {%4,%5,%6,%7}, {%8,%9}, {%0,%1,%2,%3};\n"
        : "+f"(c[0]), "+f"(c[1]), "+f"(c[2]), "+f"(c[3])
        : "r"(a[0]), "r"(a[1]), "r"(a[2]), "r"(a[3]), "r"(b[0]), "r"(b[1]));
}

__device__ __forceinline__ void split_pack(float f0, float f1, uint32_t& hi, uint32_t& lo) {
    __nv_bfloat16 h0 = __float2bfloat16_rn(f0);
    __nv_bfloat16 h1 = __float2bfloat16_rn(f1);
    float r0 = f0 - __bfloat162float(h0);
    float r1 = f1 - __bfloat162float(h1);
    __nv_bfloat162 H; H.x = h0; H.y = h1;
    __nv_bfloat162 L; L.x = __float2bfloat16_rn(r0); L.y = __float2bfloat16_rn(r1);
    hi = *reinterpret_cast<uint32_t*>(&H);
    lo = *reinterpret_cast<uint32_t*>(&L);
}

#define SP 136   // padded stride (u32) over m/n dim -> conflict-free frag LDS

// ---------------------------------------------------------------------------
// Unified NT tensor-core GEMM: C[M,N] = A[M,K] @ B[N,K]^T
// Block 128x128, 8 warps (2x4), warp tile 64x32, BK=16, double-buffered smem.
// MODE 0: proj   (A=x, B=wq/wk/wv via z, K=1024, head-major scatter epilogue)
// MODE 1: scores (A=g_q[z], B=g_k[z], K=64, scale+mask epilogue -> attn)
// MODE 2: outproj(A=g_ctx, B=wo, K=1024, plain epilogue)
// ---------------------------------------------------------------------------
template<int MODE>
__global__ void __launch_bounds__(256)
gemm_nt_kernel(const float* __restrict__ Ain, const float* __restrict__ B0,
               const float* __restrict__ B1,  const float* __restrict__ B2,
               const int* __restrict__ mask,  float* __restrict__ outp)
{
    constexpr int KD    = (MODE == 1) ? DK : DM;
    constexpr int NITER = KD / 16;

    __shared__ uint32_t AsH[2][8][SP], AsL[2][8][SP];
    __shared__ uint32_t BsH[2][8][SP], BsL[2][8][SP];

    const int t  = threadIdx.x;
    const int z  = blockIdx.z;
    const int m0 = blockIdx.y * 128;
    const int n0 = blockIdx.x * 128;

    const float* A;
    const float* B;
    if (MODE == 0)      { A = Ain; B = (z == 0) ? B0 : (z == 1) ? B1 : B2; }
    else if (MODE == 1) { A = g_q + (size_t)z * SEQ * DK; B = g_k + (size_t)z * SEQ * DK; }
    else                { A = g_ctx; B = B0; }

    const int lrow = t >> 1;
    const int kc   = (t & 1) * 8;
    const int k2b  = kc >> 1;                  // 0 or 4
    const float* pA = A + (size_t)(m0 + lrow) * KD + kc;
    const float* pB = B + (size_t)(n0 + lrow) * KD + kc;

    float4 ra0 = *(const float4*)(pA);
    float4 ra1 = *(const float4*)(pA + 4);
    float4 rb0 = *(const float4*)(pB);
    float4 rb1 = *(const float4*)(pB + 4);

    split_pack(ra0.x, ra0.y, AsH[0][k2b + 0][lrow], AsL[0][k2b + 0][lrow]);
    split_pack(ra0.z, ra0.w, AsH[0][k2b + 1][lrow], AsL[0][k2b + 1][lrow]);
    split_pack(ra1.x, ra1.y, AsH[0][k2b + 2][lrow], AsL[0][k2b + 2][lrow]);
    split_pack(ra1.z, ra1.w, AsH[0][k2b + 3][lrow], AsL[0][k2b + 3][lrow]);
    split_pack(rb0.x, rb0.y, BsH[0][k2b + 0][lrow], BsL[0][k2b + 0][lrow]);
    split_pack(rb0.z, rb0.w, BsH[0][k2b + 1][lrow], BsL[0][k2b + 1][lrow]);
    split_pack(rb1.x, rb1.y, BsH[0][k2b + 2][lrow], BsL[0][k2b + 2][lrow]);
    split_pack(rb1.z, rb1.w, BsH[0][k2b + 3][lrow], BsL[0][k2b + 3][lrow]);
    __syncthreads();

    const int warp = t >> 5, lane = t & 31;
    const int wm = (warp >> 2) * 64;
    const int wn = (warp & 3) * 32;
    const int qrow = lane >> 2, qk = lane & 3;

    float c[4][4][4] = {};

    for (int it = 0; it < NITER; ++it) {
        const int buf = it & 1;
        if (it + 1 < NITER) {
            const float* qa = pA + (it + 1) * 16;
            const float* qb = pB + (it + 1) * 16;
            ra0 = *(const float4*)(qa); ra1 = *(const float4*)(qa + 4);
            rb0 = *(const float4*)(qb); rb1 = *(const float4*)(qb + 4);
        }

        uint32_t aH[4][4], aL[4][4], bH[4][2], bL[4][2];
        #pragma unroll
        for (int mt = 0; mt < 4; mt++) {
            int m = wm + mt * 16 + qrow;
            aH[mt][0] = AsH[buf][qk][m];     aH[mt][1] = AsH[buf][qk][m + 8];
            aH[mt][2] = AsH[buf][qk + 4][m]; aH[mt][3] = AsH[buf][qk + 4][m + 8];
            aL[mt][0] = AsL[buf][qk][m];     aL[mt][1] = AsL[buf][qk][m + 8];
            aL[mt][2] = AsL[buf][qk + 4][m]; aL[mt][3] = AsL[buf][qk + 4][m + 8];
        }
        #pragma unroll
        for (int nt = 0; nt < 4; nt++) {
            int n = wn + nt * 8 + qrow;
            bH[nt][0] = BsH[buf][qk][n]; bH[nt][1] = BsH[buf][qk + 4][n];
            bL[nt][0] = BsL[buf][qk][n]; bL[nt][1] = BsL[buf][qk + 4][n];
        }
        #pragma unroll
        for (int mt = 0; mt < 4; mt++)
            #pragma unroll
            for (int nt = 0; nt < 4; nt++) {
                mma_bf16(c[mt][nt], aH[mt], bH[nt]);
                mma_bf16(c[mt][nt], aH[mt], bL[nt]);
                mma_bf16(c[mt][nt], aL[mt], bH[nt]);
            }

        if (it + 1 < NITER) {
            const int nb = buf ^ 1;
            split_pack(ra0.x, ra0.y, AsH[nb][k2b + 0][lrow], AsL[nb][k2b + 0][lrow]);
            split_pack(ra0.z, ra0.w, AsH[nb][k2b + 1][lrow], AsL[nb][k2b + 1][lrow]);
            split_pack(ra1.x, ra1.y, AsH[nb][k2b + 2][lrow], AsL[nb][k2b + 2][lrow]);
            split_pack(ra1.z, ra1.w, AsH[nb][k2b + 3][lrow], AsL[nb][k2b + 3][lrow]);
            split_pack(rb0.x, rb0.y, BsH[nb][k2b + 0][lrow], BsL[nb][k2b + 0][lrow]);
            split_pack(rb0.z, rb0.w, BsH[nb][k2b + 1][lrow], BsL[nb][k2b + 1][lrow]);
            split_pack(rb1.x, rb1.y, BsH[nb][k2b + 2][lrow], BsL[nb][k2b + 2][lrow]);
            split_pack(rb1.z, rb1.w, BsH[nb][k2b + 3][lrow], BsL[nb][k2b + 3][lrow]);
        }
        __syncthreads();
    }

    #pragma unroll
    for (int mt = 0; mt < 4; mt++) {
        #pragma unroll
        for (int nt = 0; nt < 4; nt++) {
            int mg = m0 + wm + mt * 16 + qrow;
            int ng = n0 + wn + nt * 8 + qk * 2;
            #pragma unroll
            for (int half = 0; half < 2; half++) {
                int m = mg + half * 8;
                float v0 = c[mt][nt][half * 2 + 0];
                float v1 = c[mt][nt][half * 2 + 1];
                if (MODE == 0) {
                    float* outg = (z == 0) ? g_q : (z == 1) ? g_k : g_v;
                    int b = m >> 11, s = m & (SEQ - 1);
                    int h = ng >> 6, d = ng & 63;
                    float2 w = {v0, v1};
                    *(float2*)(outg + ((size_t)(b * NH + h) * SEQ + s) * DK + d) = w;
                } else if (MODE == 1) {
                    int bb = z >> 4;
                    int mk0 = mask[bb * SEQ + ng];
                    int mk1 = mask[bb * SEQ + ng + 1];
                    float2 w;
                    w.x = mk0 ? -1e9f : v0 * 0.125f;
                    w.y = mk1 ? -1e9f : v1 * 0.125f;
                    *(float2*)(outp + ((size_t)z * SEQ + m) * SEQ + ng) = w;
                } else {
                    float2 w = {v0, v1};
                    *(float2*)(outp + (size_t)m * DM + ng) = w;
                }
            }
        }
    }
}

// ---------------------------------------------------------------------------
// FUSED softmax + ctx = softmax(scores) @ V, writing normalized attn in-place.
// Per (bh, 128-row tile):
//  Phase 1: warp w owns rows [w*16, w*16+16): coalesced sweeps for row max,
//           then exp-sum; (m, 1/s) kept in the registers of the very threads
//           that stage those rows in phase 2 (no extra sync needed).
//  Phase 2: double-buffered tensor-core loop over k; staging transforms raw
//           score -> p = exp(x-m)/s, stores p to global (in-place attn
//           output), split-packs p for the MMA against V.
// ---------------------------------------------------------------------------
__global__ void __launch_bounds__(256)
softmax_ctx_kernel(float* __restrict__ attn)
{
    __shared__ uint32_t AsH[2][8][SP], AsL[2][8][SP];
    __shared__ uint32_t BsH[2][8][72], BsL[2][8][72];

    const int t  = threadIdx.x;
    const int z  = blockIdx.z;                 // bh
    const int m0 = blockIdx.y * 128;
    float* A = attn + (size_t)z * SEQ * SEQ;
    const float* V = g_v + (size_t)z * SEQ * DK;

    const int warp = t >> 5, lane = t & 31;

    // ---- Phase 1: row max + inv exp-sum ----
    float m_mine = 0.f, inv_mine = 1.f;
    {
        const int myj = lane >> 1;             // phase-2 staging row within this warp
        for (int j = 0; j < 16; j++) {
            const float* row = A + (size_t)(m0 + warp * 16 + j) * SEQ;
            float mx = -INFINITY;
            #pragma unroll 4
            for (int cch = 0; cch < 16; cch++) {
                float4 f = *(const float4*)(row + (cch * 32 + lane) * 4);
                mx = fmaxf(fmaxf(mx, fmaxf(f.x, f.y)), fmaxf(f.z, f.w));
            }
            #pragma unroll
            for (int o = 16; o; o >>= 1) mx = fmaxf(mx, __shfl_xor_sync(0xffffffffu, mx, o));
            float s = 0.f;
            #pragma unroll 4
            for (int cch = 0; cch < 16; cch++) {
                float4 f = *(const float4*)(row + (cch * 32 + lane) * 4);
                s += __expf(f.x - mx) + __expf(f.y - mx)
                   + __expf(f.z - mx) + __expf(f.w - mx);
            }
            #pragma unroll
            for (int o = 16; o; o >>= 1) s += __shfl_xor_sync(0xffffffffu, s, o);
            if (j == myj) { m_mine = mx; inv_mine = 1.0f / s; }
        }
    }

    // ---- Phase 2: GEMM with softmax transform on the staging path ----
    const int lrow = t >> 1;
    const int kc   = (t & 1) * 8;
    const int k2b  = kc >> 1;
    float* pA = A + (size_t)(m0 + lrow) * SEQ + kc;

    float4 ra0 = *(const float4*)(pA);
    float4 ra1 = *(const float4*)(pA + 4);
    // transform + write normalized attn in place
    ra0.x = __expf(ra0.x - m_mine) * inv_mine;
    ra0.y = __expf(ra0.y - m_mine) * inv_mine;
    ra0.z = __expf(ra0.z - m_mine) * inv_mine;
    ra0.w = __expf(ra0.w - m_mine) * inv_mine;
    ra1.x = __expf(ra1.x - m_mine) * inv_mine;
    ra1.y = __expf(ra1.y - m_mine) * inv_mine;
    ra1.z = __expf(ra1.z - m_mine) * inv_mine;
    ra1.w = __expf(ra1.w - m_mine) * inv_mine;
    *(float4*)(pA)     = ra0;
    *(float4*)(pA + 4) = ra1;

    float vb[2][2];
    #pragma unroll
    for (int i = 0; i < 2; i++) {
        int p = t + 256 * i;
        int pk2 = p >> 6, pn = p & 63;
        vb[i][0] = V[(size_t)(2 * pk2 + 0) * DK + pn];
        vb[i][1] = V[(size_t)(2 * pk2 + 1) * DK + pn];
    }

    split_pack(ra0.x, ra0.y, AsH[0][k2b + 0][lrow], AsL[0][k2b + 0][lrow]);
    split_pack(ra0.z, ra0.w, AsH[0][k2b + 1][lrow], AsL[0][k2b + 1][lrow]);
    split_pack(ra1.x, ra1.y, AsH[0][k2b + 2][lrow], AsL[0][k2b + 2][lrow]);
    split_pack(ra1.z, ra1.w, AsH[0][k2b + 3][lrow], AsL[0][k2b + 3][lrow]);
    #pragma unroll
    for (int i = 0; i < 2; i++) {
        int p = t + 256 * i;
        int pk2 = p >> 6, pn = p & 63;
        split_pack(vb[i][0], vb[i][1], BsH[0][pk2][pn], BsL[0][pk2][pn]);
    }
    __syncthreads();

    const int wm = (warp >> 1) * 32;
    const int wn = (warp & 1) * 32;
    const int qrow = lane >> 2, qk = lane & 3;

    float c[2][4][4] = {};

    constexpr int NITER = SEQ / 16;            // 128
    for (int it = 0; it < NITER; ++it) {
        const int buf = it & 1;
        if (it + 1 < NITER) {
            const int k0 = (it + 1) * 16;
            float* qa = pA + k0;
            ra0 = *(const float4*)(qa); ra1 = *(const float4*)(qa + 4);
            ra0.x = __expf(ra0.x - m_mine) * inv_mine;
            ra0.y = __expf(ra0.y - m_mine) * inv_mine;
            ra0.z = __expf(ra0.z - m_mine) * inv_mine;
            ra0.w = __expf(ra0.w - m_mine) * inv_mine;
            ra1.x = __expf(ra1.x - m_mine) * inv_mine;
            ra1.y = __expf(ra1.y - m_mine) * inv_mine;
            ra1.z = __expf(ra1.z - m_mine) * inv_mine;
            ra1.w = __expf(ra1.w - m_mine) * inv_mine;
            *(float4*)(qa)     = ra0;
            *(float4*)(qa + 4) = ra1;
            #pragma unroll
            for (int i = 0; i < 2; i++) {
                int p = t + 256 * i;
                int pk2 = p >> 6, pn = p & 63;
                vb[i][0] = V[(size_t)(k0 + 2 * pk2 + 0) * DK + pn];
                vb[i][1] = V[(size_t)(k0 + 2 * pk2 + 1) * DK + pn];
            }
        }

        uint32_t aH[2][4], aL[2][4], bH[4][2], bL[4][2];
        #pragma unroll
        for (int mt = 0; mt < 2; mt++) {
            int m = wm + mt * 16 + qrow;
            aH[mt][0] = AsH[buf][qk][m];     aH[mt][1] = AsH[buf][qk][m + 8];
            aH[mt][2] = AsH[buf][qk + 4][m]; aH[mt][3] = AsH[buf][qk + 4][m + 8];
            aL[mt][0] = AsL[buf][qk][m];     aL[mt][1] = AsL[buf][qk][m + 8];
            aL[mt][2] = AsL[buf][qk + 4][m]; aL[mt][3] = AsL[buf][qk + 4][m + 8];
        }
        #pragma unroll
        for (int nt = 0; nt < 4; nt++) {
            int n = wn + nt * 8 + qrow;
            bH[nt][0] = BsH[buf][qk][n]; bH[nt][1] = BsH[buf][qk + 4][n];
            bL[nt][0] = BsL[buf][qk][n]; bL[nt][1] = BsL[buf][qk + 4][n];
        }
        #pragma unroll
        for (int mt = 0; mt < 2; mt++)
            #pragma unroll
            for (int nt = 0; nt < 4; nt++) {
                mma_bf16(c[mt][nt], aH[mt], bH[nt]);
                mma_bf16(c[mt][nt], aH[mt], bL[nt]);
                mma_bf16(c[mt][nt], aL[mt], bH[nt]);
            }

        if (it + 1 < NITER) {
            const int nb = buf ^ 1;
            split_pack(ra0.x, ra0.y, AsH[nb][k2b + 0][lrow], AsL[nb][k2b + 0][lrow]);
            split_pack(ra0.z, ra0.w, AsH[nb][k2b + 1][lrow], AsL[nb][k2b + 1][lrow]);
            split_pack(ra1.x, ra1.y, AsH[nb][k2b + 2][lrow], AsL[nb][k2b + 2][lrow]);
            split_pack(ra1.z, ra1.w, AsH[nb][k2b + 3][lrow], AsL[nb][k2b + 3][lrow]);
            #pragma unroll
            for (int i = 0; i < 2; i++) {
                int p = t + 256 * i;
                int pk2 = p >> 6, pn = p & 63;
                split_pack(vb[i][0], vb[i][1], BsH[nb][pk2][pn], BsL[nb][pk2][pn]);
            }
        }
        __syncthreads();
    }

    const int b = z >> 4, h = z & 15;
    #pragma unroll
    for (int mt = 0; mt < 2; mt++) {
        #pragma unroll
        for (int nt = 0; nt < 4; nt++) {
            int s0 = m0 + wm + mt * 16 + qrow;
            int d  = wn + nt * 8 + qk * 2;
            #pragma unroll
            for (int half = 0; half < 2; half++) {
                int s = s0 + half * 8;
                float2 w = {c[mt][nt][half * 2 + 0], c[mt][nt][half * 2 + 1]};
                *(float2*)(g_ctx + ((size_t)b * SEQ + s) * DM + h * DK + d) = w;
            }
        }
    }
}

// ---------------------------------------------------------------------------
// Launch. d_out layout: [out: 4096*1024 f32][attn: 32*2048*2048 f32]
// Inputs: x, mask, w_q, w_k, w_v, w_o
// ---------------------------------------------------------------------------
extern "C" void kernel_launch(void* const* d_in, const int* in_sizes, int n_in,
                              void* d_out, int out_size)
{
    const float* x    = (const float*)d_in[0];
    const int*   mask = (const int*)  d_in[1];
    const float* wq   = (const float*)d_in[2];
    const float* wk   = (const float*)d_in[3];
    const float* wv   = (const float*)d_in[4];
    const float* wo   = (const float*)d_in[5];

    float* out  = (float*)d_out;
    float* attn = out + (size_t)MROWS * DM;

    gemm_nt_kernel<0><<<dim3(DM / 128, MROWS / 128, 3), 256>>>(x, wq, wk, wv, nullptr, nullptr);
    gemm_nt_kernel<1><<<dim3(SEQ / 128, SEQ / 128, BH), 256>>>(nullptr, nullptr, nullptr, nullptr, mask, attn);
    softmax_ctx_kernel<<<dim3(1, SEQ / 128, BH), 256>>>(attn);
    gemm_nt_kernel<2><<<dim3(DM / 128, MROWS / 128, 1), 256>>>(nullptr, wo, nullptr, nullptr, nullptr, out);
}

// round 8
// speedup vs baseline: 1.0761x; 1.0761x over previous
#include <cuda_runtime.h>
#include <cuda_bf16.h>
#include <math.h>
#include <stdint.h>

#define BATCH 2
#define SEQ 2048
#define DM 1024
#define NH 16
#define DK 64
#define MROWS (BATCH * SEQ)          // 4096
#define BH (BATCH * NH)              // 32
#define DM2 (DM / 2)                 // 512 u32 pairs per row
#define DK2 (DK / 2)                 // 32

// Scratch (allocation-free rule: __device__ globals)
// Pre-split bf16 hi/lo operand storage (u32 = bf16x2 over a k-pair)
__device__ uint32_t g_xh[MROWS * DM2],  g_xl[MROWS * DM2];     // x split
__device__ uint32_t g_wsh[4 * DM * DM2], g_wsl[4 * DM * DM2];  // wq,wk,wv,wo split
__device__ uint32_t g_qh[BH * SEQ * DK2], g_ql[BH * SEQ * DK2];
__device__ uint32_t g_kh[BH * SEQ * DK2], g_kl[BH * SEQ * DK2];
__device__ float    g_v[BH * SEQ * DK];                        // V stays fp32 (k-pairing differs)
__device__ uint32_t g_ch[MROWS * DM2],  g_cl[MROWS * DM2];     // ctx split

// ---------------------------------------------------------------------------
// bf16 split-precision mma helpers (3xBF16 ~= fp32 accuracy, err ~1e-5)
// ---------------------------------------------------------------------------
__device__ __forceinline__ void mma_bf16(float c[4], const uint32_t a[4], const uint32_t b[2]) {
    asm volatile(
        "mma.sync.aligned.m16n8k16.row.col.f32.bf16.bf16.f32 "
        "{%0,%1,%2,%3}, {%4,%5,%6,%7}, {%8,%9}, {%0,%1,%2,%3};\n"
        : "+f"(c[0]), "+f"(c[1]), "+f"(c[2]), "+f"(c[3])
        : "r"(a[0]), "r"(a[1]), "r"(a[2]), "r"(a[3]), "r"(b[0]), "r"(b[1]));
}

__device__ __forceinline__ void split_pack(float f0, float f1, uint32_t& hi, uint32_t& lo) {
    __nv_bfloat16 h0 = __float2bfloat16_rn(f0);
    __nv_bfloat16 h1 = __float2bfloat16_rn(f1);
    float r0 = f0 - __bfloat162float(h0);
    float r1 = f1 - __bfloat162float(h1);
    __nv_bfloat162 H; H.x = h0; H.y = h1;
    __nv_bfloat162 L; L.x = __float2bfloat16_rn(r0); L.y = __float2bfloat16_rn(r1);
    hi = *reinterpret_cast<uint32_t*>(&H);
    lo = *reinterpret_cast<uint32_t*>(&L);
}

#define SP 136   // padded stride (u32) over m/n dim -> conflict-free frag LDS

// ---------------------------------------------------------------------------
// Staging: split x and the 4 weight matrices into hi/lo bf16x2 arrays. Once.
// z: 0=x, 1=wq, 2=wk, 3=wv, 4=wo
// ---------------------------------------------------------------------------
__global__ void __launch_bounds__(256)
split_all_kernel(const float* __restrict__ x,  const float* __restrict__ wq,
                 const float* __restrict__ wk, const float* __restrict__ wv,
                 const float* __restrict__ wo)
{
    const int z = blockIdx.z;
    const float* src = (z == 0) ? x : (z == 1) ? wq : (z == 2) ? wk : (z == 3) ? wv : wo;
    uint32_t* dh = (z == 0) ? g_xh : g_wsh + (size_t)(z - 1) * DM * DM2;
    uint32_t* dl = (z == 0) ? g_xl : g_wsl + (size_t)(z - 1) * DM * DM2;
    const int n4 = ((z == 0) ? MROWS * DM : DM * DM) / 4;   // float4 count

    for (int i = blockIdx.x * blockDim.x + threadIdx.x; i < n4;
         i += gridDim.x * blockDim.x) {
        float4 f = ((const float4*)src)[i];
        uint32_t h0, l0, h1, l1;
        split_pack(f.x, f.y, h0, l0);
        split_pack(f.z, f.w, h1, l1);
        dh[i * 2]     = h0; dh[i * 2 + 1] = h1;
        dl[i * 2]     = l0; dl[i * 2 + 1] = l1;
    }
}

// ---------------------------------------------------------------------------
// Pre-split NT tensor-core GEMM: C[M,N] = A[M,K] @ B[N,K]^T, operands already
// in hi/lo bf16x2 form. Loader = pure LDG.128 -> STS (no conversion math).
// Block 128x128, 8 warps (2x4), warp tile 64x32, BK=16, double-buffered.
// SMODE 0: proj   (A=x-split, B=wq/wk/wv-split via z; epi: q/k split, v fp32)
// SMODE 1: scores (A=q-split[z], B=k-split[z], K=64; epi: scale+mask -> attn)
// SMODE 2: outproj(A=ctx-split, B=wo-split; epi: fp32 out)
// ---------------------------------------------------------------------------
template<int SMODE>
__global__ void __launch_bounds__(256)
gemm_bb_kernel(const int* __restrict__ mask, float* __restrict__ attn,
               float* __restrict__ out)
{
    constexpr int KD    = (SMODE == 1) ? DK : DM;
    constexpr int KD2   = KD / 2;
    constexpr int NITER = KD / 16;

    __shared__ uint32_t AsH[2][8][SP], AsL[2][8][SP];
    __shared__ uint32_t BsH[2][8][SP], BsL[2][8][SP];

    const int t  = threadIdx.x;
    const int z  = blockIdx.z;
    const int m0 = blockIdx.y * 128;
    const int n0 = blockIdx.x * 128;

    const uint32_t *Ah, *Al, *Bh, *Bl;
    if (SMODE == 0) {
        Ah = g_xh; Al = g_xl;
        Bh = g_wsh + (size_t)z * DM * DM2;
        Bl = g_wsl + (size_t)z * DM * DM2;
    } else if (SMODE == 1) {
        Ah = g_qh + (size_t)z * SEQ * DK2; Al = g_ql + (size_t)z * SEQ * DK2;
        Bh = g_kh + (size_t)z * SEQ * DK2; Bl = g_kl + (size_t)z * SEQ * DK2;
    } else {
        Ah = g_ch; Al = g_cl;
        Bh = g_wsh + (size_t)3 * DM * DM2;
        Bl = g_wsl + (size_t)3 * DM * DM2;
    }

    const int lrow = t >> 1;            // 0..127
    const int kc2  = (t & 1) * 4;       // u32 offset within 8-u32 k-chunk
    const uint32_t* pAh = Ah + (size_t)(m0 + lrow) * KD2 + kc2;
    const uint32_t* pAl = Al + (size_t)(m0 + lrow) * KD2 + kc2;
    const uint32_t* pBh = Bh + (size_t)(n0 + lrow) * KD2 + kc2;
    const uint32_t* pBl = Bl + (size_t)(n0 + lrow) * KD2 + kc2;

    uint4 ah = *(const uint4*)pAh;
    uint4 al = *(const uint4*)pAl;
    uint4 bh = *(const uint4*)pBh;
    uint4 bl = *(const uint4*)pBl;

    AsH[0][kc2 + 0][lrow] = ah.x; AsH[0][kc2 + 1][lrow] = ah.y;
    AsH[0][kc2 + 2][lrow] = ah.z; AsH[0][kc2 + 3][lrow] = ah.w;
    AsL[0][kc2 + 0][lrow] = al.x; AsL[0][kc2 + 1][lrow] = al.y;
    AsL[0][kc2 + 2][lrow] = al.z; AsL[0][kc2 + 3][lrow] = al.w;
    BsH[0][kc2 + 0][lrow] = bh.x; BsH[0][kc2 + 1][lrow] = bh.y;
    BsH[0][kc2 + 2][lrow] = bh.z; BsH[0][kc2 + 3][lrow] = bh.w;
    BsL[0][kc2 + 0][lrow] = bl.x; BsL[0][kc2 + 1][lrow] = bl.y;
    BsL[0][kc2 + 2][lrow] = bl.z; BsL[0][kc2 + 3][lrow] = bl.w;
    __syncthreads();

    const int warp = t >> 5, lane = t & 31;
    const int wm = (warp >> 2) * 64;
    const int wn = (warp & 3) * 32;
    const int qrow = lane >> 2, qk = lane & 3;

    float c[4][4][4] = {};

    for (int it = 0; it < NITER; ++it) {
        const int buf = it & 1;
        if (it + 1 < NITER) {
            const int o = (it + 1) * 8;
            ah = *(const uint4*)(pAh + o);
            al = *(const uint4*)(pAl + o);
            bh = *(const uint4*)(pBh + o);
            bl = *(const uint4*)(pBl + o);
        }

        uint32_t aH[4][4], aL[4][4], bHf[4][2], bLf[4][2];
        #pragma unroll
        for (int mt = 0; mt < 4; mt++) {
            int m = wm + mt * 16 + qrow;
            aH[mt][0] = AsH[buf][qk][m];     aH[mt][1] = AsH[buf][qk][m + 8];
            aH[mt][2] = AsH[buf][qk + 4][m]; aH[mt][3] = AsH[buf][qk + 4][m + 8];
            aL[mt][0] = AsL[buf][qk][m];     aL[mt][1] = AsL[buf][qk][m + 8];
            aL[mt][2] = AsL[buf][qk + 4][m]; aL[mt][3] = AsL[buf][qk + 4][m + 8];
        }
        #pragma unroll
        for (int nt = 0; nt < 4; nt++) {
            int n = wn + nt * 8 + qrow;
            bHf[nt][0] = BsH[buf][qk][n]; bHf[nt][1] = BsH[buf][qk + 4][n];
            bLf[nt][0] = BsL[buf][qk][n]; bLf[nt][1] = BsL[buf][qk + 4][n];
        }
        #pragma unroll
        for (int mt = 0; mt < 4; mt++)
            #pragma unroll
            for (int nt = 0; nt < 4; nt++) {
                mma_bf16(c[mt][nt], aH[mt], bHf[nt]);
                mma_bf16(c[mt][nt], aH[mt], bLf[nt]);
                mma_bf16(c[mt][nt], aL[mt], bHf[nt]);
            }

        if (it + 1 < NITER) {
            const int nb = buf ^ 1;
            AsH[nb][kc2 + 0][lrow] = ah.x; AsH[nb][kc2 + 1][lrow] = ah.y;
            AsH[nb][kc2 + 2][lrow] = ah.z; AsH[nb][kc2 + 3][lrow] = ah.w;
            AsL[nb][kc2 + 0][lrow] = al.x; AsL[nb][kc2 + 1][lrow] = al.y;
            AsL[nb][kc2 + 2][lrow] = al.z; AsL[nb][kc2 + 3][lrow] = al.w;
            BsH[nb][kc2 + 0][lrow] = bh.x; BsH[nb][kc2 + 1][lrow] = bh.y;
            BsH[nb][kc2 + 2][lrow] = bh.z; BsH[nb][kc2 + 3][lrow] = bh.w;
            BsL[nb][kc2 + 0][lrow] = bl.x; BsL[nb][kc2 + 1][lrow] = bl.y;
            BsL[nb][kc2 + 2][lrow] = bl.z; BsL[nb][kc2 + 3][lrow] = bl.w;
        }
        __syncthreads();
    }

    #pragma unroll
    for (int mt = 0; mt < 4; mt++) {
        #pragma unroll
        for (int nt = 0; nt < 4; nt++) {
            int mg = m0 + wm + mt * 16 + qrow;
            int ng = n0 + wn + nt * 8 + qk * 2;
            #pragma unroll
            for (int half = 0; half < 2; half++) {
                int m = mg + half * 8;
                float v0 = c[mt][nt][half * 2 + 0];
                float v1 = c[mt][nt][half * 2 + 1];
                if (SMODE == 0) {
                    int b = m >> 11, s = m & (SEQ - 1);
                    int h = ng >> 6, d = ng & 63;
                    if (z == 2) {
                        float2 w = {v0, v1};
                        *(float2*)(g_v + ((size_t)(b * NH + h) * SEQ + s) * DK + d) = w;
                    } else {
                        uint32_t hi, lo;
                        split_pack(v0, v1, hi, lo);
                        size_t idx = ((size_t)(b * NH + h) * SEQ + s) * DK2 + (d >> 1);
                        if (z == 0) { g_qh[idx] = hi; g_ql[idx] = lo; }
                        else        { g_kh[idx] = hi; g_kl[idx] = lo; }
                    }
                } else if (SMODE == 1) {
                    int bb = z >> 4;
                    int mk0 = mask[bb * SEQ + ng];
                    int mk1 = mask[bb * SEQ + ng + 1];
                    float2 w;
                    w.x = mk0 ? -1e9f : v0 * 0.125f;
                    w.y = mk1 ? -1e9f : v1 * 0.125f;
                    *(float2*)(attn + ((size_t)z * SEQ + m) * SEQ + ng) = w;
                } else {
                    float2 w = {v0, v1};
                    *(float2*)(out + (size_t)m * DM + ng) = w;
                }
            }
        }
    }
}

// ---------------------------------------------------------------------------
// Row softmax in place. One block (256 thr) per row of 2048. (proven R5 code)
// ---------------------------------------------------------------------------
__global__ void __launch_bounds__(256)
softmax_kernel(float* __restrict__ attn)
{
    float* p = attn + (size_t)blockIdx.x * SEQ;
    const int t = threadIdx.x;

    float vals[8];
    float mx = -INFINITY;
    #pragma unroll
    for (int c = 0; c < 2; c++) {
        float4 f = *(float4*)(p + c * 1024 + t * 4);
        vals[c * 4 + 0] = f.x; vals[c * 4 + 1] = f.y;
        vals[c * 4 + 2] = f.z; vals[c * 4 + 3] = f.w;
    }
    #pragma unroll
    for (int i = 0; i < 8; i++) mx = fmaxf(mx, vals[i]);

    __shared__ float sm[8];
    #pragma unroll
    for (int o = 16; o; o >>= 1) mx = fmaxf(mx, __shfl_xor_sync(0xffffffffu, mx, o));
    if ((t & 31) == 0) sm[t >> 5] = mx;
    __syncthreads();
    if (t < 32) {
        float v = (t < 8) ? sm[t] : -INFINITY;
        #pragma unroll
        for (int o = 4; o; o >>= 1) v = fmaxf(v, __shfl_xor_sync(0xffffffffu, v, o));
        if (t == 0) sm[0] = v;
    }
    __syncthreads();
    mx = sm[0];

    float s = 0.f;
    #pragma unroll
    for (int i = 0; i < 8; i++) { vals[i] = __expf(vals[i] - mx); s += vals[i]; }

    __shared__ float sm2[8];
    #pragma unroll
    for (int o = 16; o; o >>= 1) s += __shfl_xor_sync(0xffffffffu, s, o);
    if ((t & 31) == 0) sm2[t >> 5] = s;
    __syncthreads();
    if (t < 32) {
        float v = (t < 8) ? sm2[t] : 0.f;
        #pragma unroll
        for (int o = 4; o; o >>= 1) v += __shfl_xor_sync(0xffffffffu, v, o);
        if (t == 0) sm2[0] = v;
    }
    __syncthreads();
    const float inv = 1.0f / sm2[0];

    #pragma unroll
    for (int c = 0; c < 2; c++) {
        float4 f;
        f.x = vals[c * 4 + 0] * inv; f.y = vals[c * 4 + 1] * inv;
        f.z = vals[c * 4 + 2] * inv; f.w = vals[c * 4 + 3] * inv;
        *(float4*)(p + c * 1024 + t * 4) = f;
    }
}

// ---------------------------------------------------------------------------
// ctx = attn @ V  (NN).  Per head: M=2048, N=64, K=2048. (proven R5 code,
// except the epilogue now writes ctx in pre-split hi/lo form for outproj.)
// ---------------------------------------------------------------------------
__global__ void __launch_bounds__(256)
ctx_kernel(const float* __restrict__ attn)
{
    __shared__ uint32_t AsH[2][8][SP], AsL[2][8][SP];
    __shared__ uint32_t BsH[2][8][72], BsL[2][8][72];

    const int t  = threadIdx.x;
    const int z  = blockIdx.z;                 // bh
    const int m0 = blockIdx.y * 128;
    const float* A = attn + (size_t)z * SEQ * SEQ;
    const float* V = g_v  + (size_t)z * SEQ * DK;

    const int lrow = t >> 1;
    const int kc   = (t & 1) * 8;
    const int k2b  = kc >> 1;
    const float* pA = A + (size_t)(m0 + lrow) * SEQ + kc;

    float4 ra0 = *(const float4*)(pA);
    float4 ra1 = *(const float4*)(pA + 4);
    float vb[2][2];
    #pragma unroll
    for (int i = 0; i < 2; i++) {
        int p = t + 256 * i;
        int pk2 = p >> 6, pn = p & 63;
        vb[i][0] = V[(size_t)(2 * pk2 + 0) * DK + pn];
        vb[i][1] = V[(size_t)(2 * pk2 + 1) * DK + pn];
    }

    split_pack(ra0.x, ra0.y, AsH[0][k2b + 0][lrow], AsL[0][k2b + 0][lrow]);
    split_pack(ra0.z, ra0.w, AsH[0][k2b + 1][lrow], AsL[0][k2b + 1][lrow]);
    split_pack(ra1.x, ra1.y, AsH[0][k2b + 2][lrow], AsL[0][k2b + 2][lrow]);
    split_pack(ra1.z, ra1.w, AsH[0][k2b + 3][lrow], AsL[0][k2b + 3][lrow]);
    #pragma unroll
    for (int i = 0; i < 2; i++) {
        int p = t + 256 * i;
        int pk2 = p >> 6, pn = p & 63;
        split_pack(vb[i][0], vb[i][1], BsH[0][pk2][pn], BsL[0][pk2][pn]);
    }
    __syncthreads();

    const int warp = t >> 5, lane = t & 31;
    const int wm = (warp >> 1) * 32;
    const int wn = (warp & 1) * 32;
    const int qrow = lane >> 2, qk = lane & 3;

    float c[2][4][4] = {};

    constexpr int NITER = SEQ / 16;            // 128
    for (int it = 0; it < NITER; ++it) {
        const int buf = it & 1;
        if (it + 1 < NITER) {
            const int k0 = (it + 1) * 16;
            const float* qa = pA + k0;
            ra0 = *(const float4*)(qa); ra1 = *(const float4*)(qa + 4);
            #pragma unroll
            for (int i = 0; i < 2; i++) {
                int p = t + 256 * i;
                int pk2 = p >> 6, pn = p & 63;
                vb[i][0] = V[(size_t)(k0 + 2 * pk2 + 0) * DK + pn];
                vb[i][1] = V[(size_t)(k0 + 2 * pk2 + 1) * DK + pn];
            }
        }

        uint32_t aH[2][4], aL[2][4], bH[4][2], bL[4][2];
        #pragma unroll
        for (int mt = 0; mt < 2; mt++) {
            int m = wm + mt * 16 + qrow;
            aH[mt][0] = AsH[buf][qk][m];     aH[mt][1] = AsH[buf][qk][m + 8];
            aH[mt][2] = AsH[buf][qk + 4][m]; aH[mt][3] = AsH[buf][qk + 4][m + 8];
            aL[mt][0] = AsL[buf][qk][m];     aL[mt][1] = AsL[buf][qk][m + 8];
            aL[mt][2] = AsL[buf][qk + 4][m]; aL[mt][3] = AsL[buf][qk + 4][m + 8];
        }
        #pragma unroll
        for (int nt = 0; nt < 4; nt++) {
            int n = wn + nt * 8 + qrow;
            bH[nt][0] = BsH[buf][qk][n]; bH[nt][1] = BsH[buf][qk + 4][n];
            bL[nt][0] = BsL[buf][qk][n]; bL[nt][1] = BsL[buf][qk + 4][n];
        }
        #pragma unroll
        for (int mt = 0; mt < 2; mt++)
            #pragma unroll
            for (int nt = 0; nt < 4; nt++) {
                mma_bf16(c[mt][nt], aH[mt], bH[nt]);
                mma_bf16(c[mt][nt], aH[mt], bL[nt]);
                mma_bf16(c[mt][nt], aL[mt], bH[nt]);
            }

        if (it + 1 < NITER) {
            const int nb = buf ^ 1;
            split_pack(ra0.x, ra0.y, AsH[nb][k2b + 0][lrow], AsL[nb][k2b + 0][lrow]);
            split_pack(ra0.z, ra0.w, AsH[nb][k2b + 1][lrow], AsL[nb][k2b + 1][lrow]);
            split_pack(ra1.x, ra1.y, AsH[nb][k2b + 2][lrow], AsL[nb][k2b + 2][lrow]);
            split_pack(ra1.z, ra1.w, AsH[nb][k2b + 3][lrow], AsL[nb][k2b + 3][lrow]);
            #pragma unroll
            for (int i = 0; i < 2; i++) {
                int p = t + 256 * i;
                int pk2 = p >> 6, pn = p & 63;
                split_pack(vb[i][0], vb[i][1], BsH[nb][pk2][pn], BsL[nb][pk2][pn]);
            }
        }
        __syncthreads();
    }

    const int b = z >> 4, h = z & 15;
    #pragma unroll
    for (int mt = 0; mt < 2; mt++) {
        #pragma unroll
        for (int nt = 0; nt < 4; nt++) {
            int s0 = m0 + wm + mt * 16 + qrow;
            int d  = wn + nt * 8 + qk * 2;
            #pragma unroll
            for (int half = 0; half < 2; half++) {
                int s = s0 + half * 8;
                uint32_t hi, lo;
                split_pack(c[mt][nt][half * 2 + 0], c[mt][nt][half * 2 + 1], hi, lo);
                size_t idx = ((size_t)b * SEQ + s) * DM2 + ((h * DK + d) >> 1);
                g_ch[idx] = hi;
                g_cl[idx] = lo;
            }
        }
    }
}

// ---------------------------------------------------------------------------
// Launch. d_out layout: [out: 4096*1024 f32][attn: 32*2048*2048 f32]
// Inputs: x, mask, w_q, w_k, w_v, w_o
// ---------------------------------------------------------------------------
extern "C" void kernel_launch(void* const* d_in, const int* in_sizes, int n_in,
                              void* d_out, int out_size)
{
    const float* x    = (const float*)d_in[0];
    const int*   mask = (const int*)  d_in[1];
    const float* wq   = (const float*)d_in[2];
    const float* wk   = (const float*)d_in[3];
    const float* wv   = (const float*)d_in[4];
    const float* wo   = (const float*)d_in[5];

    float* out  = (float*)d_out;
    float* attn = out + (size_t)MROWS * DM;

    split_all_kernel<<<dim3(1024, 1, 5), 256>>>(x, wq, wk, wv, wo);
    gemm_bb_kernel<0><<<dim3(DM / 128, MROWS / 128, 3), 256>>>(mask, attn, out);
    gemm_bb_kernel<1><<<dim3(SEQ / 128, SEQ / 128, BH), 256>>>(mask, attn, out);
    softmax_kernel<<<BH * SEQ, 256>>>(attn);
    ctx_kernel<<<dim3(1, SEQ / 128, BH), 256>>>(attn);
    gemm_bb_kernel<2><<<dim3(DM / 128, MROWS / 128, 1), 256>>>(mask, attn, out);
}